// round 4
// baseline (speedup 1.0000x reference)
#include <cuda_runtime.h>

// mean_var_norm — (B=64, F=256, T=4000) fp32.
// Persistent CTAs (grid=296), 256 threads, 2 rows/pair, 4 float4/row/thread.
// Register double buffering: next pair's loads are issued BEFORE the current
// pair's reduce+store, so the reduction bubble is always covered by
// outstanding reads. Streaming cache hints (no reuse).

#define BN 64
#define FN 256
#define TN 4000
#define FQ (TN / 4)            // 1000 float4 per row
#define THREADS 256
#define NW (THREADS / 32)      // 8 warps
#define VR 4                   // float4 per row per thread (256*4=1024 >= 1000)
#define NPAIRS ((BN * FN) / 2) // 8192
#define GRID 296               // 2 CTAs/SM * 148 SMs — persistent

__device__ __forceinline__ void load_pair(const float* __restrict__ x,
                                          int pair, int tid,
                                          float4 (&va)[VR], float4 (&vb)[VR]) {
    const float4* __restrict__ xa =
        reinterpret_cast<const float4*>(x + (long long)(pair * 2) * TN);
    const float4* __restrict__ xb = xa + FQ;
    #pragma unroll
    for (int k = 0; k < VR; k++) {
        const int i4 = tid + k * THREADS;
        if (i4 < FQ) va[k] = __ldcs(&xa[i4]);
    }
    #pragma unroll
    for (int k = 0; k < VR; k++) {
        const int i4 = tid + k * THREADS;
        if (i4 < FQ) vb[k] = __ldcs(&xb[i4]);
    }
}

__device__ __forceinline__ void process_pair(const float* __restrict__ lengths,
                                             float* __restrict__ out,
                                             int pair, int tid,
                                             float4 (&va)[VR], float4 (&vb)[VR],
                                             float (&red)[4][NW], float (&bc)[4]) {
    const int rowA = pair * 2;
    const int b    = rowA >> 8;            // FN = 256
    const float nf = rintf(__ldg(&lengths[b]) * (float)TN);  // matches jnp.round
    const int   ni = (int)nf;

    float sA = 0.0f, ssA = 0.0f, sB = 0.0f, ssB = 0.0f;
    #pragma unroll
    for (int k = 0; k < VR; k++) {
        const int i4 = tid + k * THREADS;
        if (i4 < FQ) {
            const int t0 = i4 * 4;
            if (t0 + 3 < ni) {
                sA  += va[k].x + va[k].y + va[k].z + va[k].w;
                ssA += va[k].x * va[k].x + va[k].y * va[k].y
                     + va[k].z * va[k].z + va[k].w * va[k].w;
                sB  += vb[k].x + vb[k].y + vb[k].z + vb[k].w;
                ssB += vb[k].x * vb[k].x + vb[k].y * vb[k].y
                     + vb[k].z * vb[k].z + vb[k].w * vb[k].w;
            } else if (t0 < ni) {
                if (t0 + 0 < ni) { sA += va[k].x; ssA += va[k].x * va[k].x;
                                   sB += vb[k].x; ssB += vb[k].x * vb[k].x; }
                if (t0 + 1 < ni) { sA += va[k].y; ssA += va[k].y * va[k].y;
                                   sB += vb[k].y; ssB += vb[k].y * vb[k].y; }
                if (t0 + 2 < ni) { sA += va[k].z; ssA += va[k].z * va[k].z;
                                   sB += vb[k].z; ssB += vb[k].z * vb[k].z; }
                if (t0 + 3 < ni) { sA += va[k].w; ssA += va[k].w * va[k].w;
                                   sB += vb[k].w; ssB += vb[k].w * vb[k].w; }
            }
        }
    }

    #pragma unroll
    for (int off = 16; off > 0; off >>= 1) {
        sA  += __shfl_xor_sync(0xFFFFFFFFu, sA,  off);
        ssA += __shfl_xor_sync(0xFFFFFFFFu, ssA, off);
        sB  += __shfl_xor_sync(0xFFFFFFFFu, sB,  off);
        ssB += __shfl_xor_sync(0xFFFFFFFFu, ssB, off);
    }

    const int wid  = tid >> 5;
    const int lane = tid & 31;
    if (lane == 0) {
        red[0][wid] = sA; red[1][wid] = ssA;
        red[2][wid] = sB; red[3][wid] = ssB;
    }
    __syncthreads();

    if (tid < 2) {
        float sum = 0.0f, sumsq = 0.0f;
        #pragma unroll
        for (int w = 0; w < NW; w++) {
            sum   += red[2 * tid + 0][w];
            sumsq += red[2 * tid + 1][w];
        }
        const float mean = sum / nf;
        float var = (sumsq - nf * mean * mean) / (nf - 1.0f);
        var = fmaxf(var, 0.0f);
        bc[2 * tid + 0] = mean;
        bc[2 * tid + 1] = 1.0f / fmaxf(sqrtf(var), 1e-10f);
    }
    __syncthreads();

    const float meanA = bc[0], istdA = bc[1];
    const float meanB = bc[2], istdB = bc[3];

    float4* __restrict__ oa =
        reinterpret_cast<float4*>(out + (long long)rowA * TN);
    float4* __restrict__ ob = oa + FQ;

    #pragma unroll
    for (int k = 0; k < VR; k++) {
        const int i4 = tid + k * THREADS;
        if (i4 < FQ) {
            float4 o;
            o.x = (va[k].x - meanA) * istdA;
            o.y = (va[k].y - meanA) * istdA;
            o.z = (va[k].z - meanA) * istdA;
            o.w = (va[k].w - meanA) * istdA;
            __stcs(&oa[i4], o);
            float4 p;
            p.x = (vb[k].x - meanB) * istdB;
            p.y = (vb[k].y - meanB) * istdB;
            p.z = (vb[k].z - meanB) * istdB;
            p.w = (vb[k].w - meanB) * istdB;
            __stcs(&ob[i4], p);
        }
    }
    // smem reuse across iterations is safe: red/bc writers are ordered by the
    // two __syncthreads above relative to all prior readers.
    __syncthreads();
}

__global__ __launch_bounds__(THREADS)
void mvn_kernel(const float* __restrict__ x,
                const float* __restrict__ lengths,
                float* __restrict__ out) {
    const int tid = threadIdx.x;

    __shared__ float red[4][NW];
    __shared__ float bc[4];

    float4 vaA[VR], vbA[VR];   // buffer A
    float4 vaB[VR], vbB[VR];   // buffer B

    int p = blockIdx.x;
    if (p >= NPAIRS) return;

    load_pair(x, p, tid, vaA, vbA);

    while (true) {
        // ---- iteration using buffer A; prefetch next pair into buffer B ----
        int pn = p + GRID;
        if (pn < NPAIRS) load_pair(x, pn, tid, vaB, vbB);
        process_pair(lengths, out, p, tid, vaA, vbA, red, bc);
        p = pn;
        if (p >= NPAIRS) break;

        // ---- iteration using buffer B; prefetch next pair into buffer A ----
        pn = p + GRID;
        if (pn < NPAIRS) load_pair(x, pn, tid, vaA, vbA);
        process_pair(lengths, out, p, tid, vaB, vbB, red, bc);
        p = pn;
        if (p >= NPAIRS) break;
    }
}

extern "C" void kernel_launch(void* const* d_in, const int* in_sizes, int n_in,
                              void* d_out, int out_size) {
    const float* x       = (const float*)d_in[0];
    const float* lengths = (const float*)d_in[1];
    float* out           = (float*)d_out;

    mvn_kernel<<<GRID, THREADS>>>(x, lengths, out);
}